// round 2
// baseline (speedup 1.0000x reference)
#include <cuda_runtime.h>

#define EMB_DIM 128
#define NB_WORDS 100000
#define ROWS_PER_THREAD 4

// out[b][e] = W[e * NB_WORDS + elt[b]] + bias[e]
// 512 threads = 4 sub-groups of 128 (one per embedding lane set),
// each thread handles 4 batch rows -> 16 rows per block, MLP=4 gathers/thread.
__global__ void time_embedding_kernel(const int* __restrict__ elt,
                                      const float* __restrict__ W,
                                      const float* __restrict__ bias,
                                      float* __restrict__ out,
                                      int batch) {
    const int e   = threadIdx.x & (EMB_DIM - 1);   // 0..127
    const int sub = threadIdx.x >> 7;              // 0..3
    const int row0 = blockIdx.x * (4 * ROWS_PER_THREAD) + sub * ROWS_PER_THREAD;

    const float bv = __ldg(&bias[e]);

    // Front-batch the index loads (uniform per warp -> broadcast).
    int idx[ROWS_PER_THREAD];
    #pragma unroll
    for (int k = 0; k < ROWS_PER_THREAD; k++) {
        int b = row0 + k;
        idx[k] = (b < batch) ? __ldg(&elt[b]) : 0;
    }

    // Front-batch the 4 independent scattered gathers (MLP=4),
    // L2-only caching: zero L1 reuse for these.
    float w[ROWS_PER_THREAD];
    #pragma unroll
    for (int k = 0; k < ROWS_PER_THREAD; k++) {
        w[k] = __ldcg(&W[(size_t)e * NB_WORDS + idx[k]]);
    }

    #pragma unroll
    for (int k = 0; k < ROWS_PER_THREAD; k++) {
        int b = row0 + k;
        if (b < batch) out[(size_t)b * EMB_DIM + e] = w[k] + bv;
    }
}

extern "C" void kernel_launch(void* const* d_in, const int* in_sizes, int n_in,
                              void* d_out, int out_size) {
    const int* elt  = (const int*)d_in[0];
    const float* W  = (const float*)d_in[1];
    const float* bv = (const float*)d_in[2];
    float* out      = (float*)d_out;

    const int batch = in_sizes[0];                      // 4096
    const int rows_per_block = 4 * ROWS_PER_THREAD;     // 16
    const int blocks = (batch + rows_per_block - 1) / rows_per_block;
    time_embedding_kernel<<<blocks, 512>>>(elt, W, bv, out, batch);
}